// round 9
// baseline (speedup 1.0000x reference)
#include <cuda_runtime.h>
#include <cuda_fp16.h>
#include <cuda_bf16.h>

#define TT 12
#define CC 32
#define MAXN 131072

// ---- bit-cast helpers (nvcc lacks __half2_as_uint / __uint_as_half2) ----
__device__ __forceinline__ unsigned h2_as_u32(__half2 h) {
    union { __half2 h; unsigned u; } cvt; cvt.h = h; return cvt.u;
}
__device__ __forceinline__ __half2 u32_as_h2(unsigned u) {
    union { unsigned u; __half2 h; } cvt; cvt.u = u; return cvt.h;
}

// ---- scratch (static device globals; zero-initialized at load; kept zeroed by k_final) ----
__device__ float g_deg[MAXN];                       // Σ incoming w; re-zeroed by k_final
__device__ float g_dinv[MAXN];
__device__ __align__(128) uint4 g_yh[MAXN * 2];     // f16 y rows: 16 halves (12 used) = 32B, sector-aligned
__device__ float g_agg[MAXN * TT];                  // scattered Σ w*y[s] (f32); re-zeroed by k_final
__device__ float g_az[CC], g_ah[CC], g_bz[CC], g_bh[CC];
__device__ float g_probs[TT];                       // 0.5 * softmax(att)
__device__ float g_hw[CC];
__device__ float g_hb;

__device__ __forceinline__ unsigned tanh2_fast(unsigned x) {  // tanh.approx on a half2 pair
    unsigned y;
    asm("tanh.approx.f16x2 %0, %1;" : "=r"(y) : "r"(x));
    return y;
}

// vectorized global reduction: 4 floats per op
__device__ __forceinline__ void red4(float* p, float a, float b, float c, float d) {
    asm volatile("red.global.add.v4.f32 [%0], {%1, %2, %3, %4};"
                 :: "l"(p), "f"(a), "f"(b), "f"(c), "f"(d) : "memory");
}

// ---- K1: deg accumulation (blocks [0, degBlocks)) + consts fold (block degBlocks) ----
__global__ void k_deg_consts(const int* __restrict__ ei, const float* __restrict__ ew, int e,
                             int degBlocks,
                             const float* __restrict__ w_z, const float* __restrict__ b_z,
                             const float* __restrict__ w_h, const float* __restrict__ b_h,
                             const float* __restrict__ lw_z, const float* __restrict__ lb_z,
                             const float* __restrict__ lw_h, const float* __restrict__ lb_h,
                             const float* __restrict__ att,
                             const float* __restrict__ head_w, const float* __restrict__ head_b) {
    if (blockIdx.x < (unsigned)degBlocks) {
        int base = (blockIdx.x * blockDim.x + threadIdx.x) * 4;
        if (base + 3 < e) {
            int4   d = *reinterpret_cast<const int4*>(ei + e + base);
            float4 w = *reinterpret_cast<const float4*>(ew + base);
            atomicAdd(&g_deg[d.x], w.x);
            atomicAdd(&g_deg[d.y], w.y);
            atomicAdd(&g_deg[d.z], w.z);
            atomicAdd(&g_deg[d.w], w.w);
        } else {
            for (int i = base; i < e; i++) atomicAdd(&g_deg[ei[e + i]], ew[i]);
        }
        return;
    }
    // ---- consts block ----
    int o = threadIdx.x;
    if (o < CC) {
        float az = 0.f, bz = 0.f, ah = 0.f, bh = 0.f;
        const float* rz = lw_z + o * 2 * CC;   // torch layout [C, 2C]; first C cols used
        const float* rh = lw_h + o * 2 * CC;
        #pragma unroll
        for (int c = 0; c < CC; c++) {
            az += w_z[c] * rz[c];
            bz += b_z[c] * rz[c];
            ah += w_h[c] * rh[c];
            bh += b_h[c] * rh[c];
        }
        g_az[o] = az; g_bz[o] = bz + lb_z[o];
        g_ah[o] = ah; g_bh[o] = bh + lb_h[o];
        g_hw[o] = head_w[o];
    }
    if (o == 0) {
        float m = -1e30f;
        for (int t = 0; t < TT; t++) m = fmaxf(m, att[t]);
        float ex[TT]; float sum = 0.f;
        for (int t = 0; t < TT; t++) { ex[t] = expf(att[t] - m); sum += ex[t]; }
        for (int t = 0; t < TT; t++) g_probs[t] = 0.5f * ex[t] / sum;  // fold 0.5 of (1-z)
        g_hb = head_b[0];
    }
}

// ---- K2: dinv + f16 y row ; one thread per node ----
__global__ void k_dinv_y(const float* __restrict__ x, int n) {
    int i = blockIdx.x * blockDim.x + threadIdx.x;
    if (i >= n) return;
    float di = rsqrtf(1.0f + g_deg[i]);   // +1 = self-loop weight; always > 0
    g_dinv[i] = di;
    const float4* xr = reinterpret_cast<const float4*>(x + (size_t)i * TT);
    float4 v0 = __ldg(xr + 0), v1 = __ldg(xr + 1), v2 = __ldg(xr + 2);
    uint4 a, b;
    a.x = h2_as_u32(__floats2half2_rn(di * v0.x, di * v0.y));
    a.y = h2_as_u32(__floats2half2_rn(di * v0.z, di * v0.w));
    a.z = h2_as_u32(__floats2half2_rn(di * v1.x, di * v1.y));
    a.w = h2_as_u32(__floats2half2_rn(di * v1.z, di * v1.w));
    b.x = h2_as_u32(__floats2half2_rn(di * v2.x, di * v2.y));
    b.y = h2_as_u32(__floats2half2_rn(di * v2.z, di * v2.w));
    b.z = 0u; b.w = 0u;                       // pad halves 12..15
    g_yh[i * 2 + 0] = a;
    g_yh[i * 2 + 1] = b;
}

// ---- K3: cooperative 2-lane edge scatter  agg[d,:] += w * y[s,:] ----
// Row is one 32B sector (16 halves). lane part0 loads first 16B (t0..7, 2 red4s);
// part1 loads next 8B (t8..11, 1 red4). 16 edges per warp, all lanes used.
__global__ void k_scatter2h(const int* __restrict__ ei, const float* __restrict__ ew, int e) {
    int tid = blockIdx.x * blockDim.x + threadIdx.x;
    int eid = tid >> 1;
    int part = tid & 1;
    if (eid >= e) return;
    int s = __ldg(ei + eid);
    int d = __ldg(ei + e + eid);
    float w = __ldg(ew + eid);
    const char* row = reinterpret_cast<const char*>(g_yh + (size_t)s * 2);
    float* ag = g_agg + (size_t)d * TT;
    if (part == 0) {
        uint4 h8 = __ldg(reinterpret_cast<const uint4*>(row));
        float2 f0 = __half22float2(u32_as_h2(h8.x));
        float2 f1 = __half22float2(u32_as_h2(h8.y));
        float2 f2 = __half22float2(u32_as_h2(h8.z));
        float2 f3 = __half22float2(u32_as_h2(h8.w));
        red4(ag + 0, w * f0.x, w * f0.y, w * f1.x, w * f1.y);
        red4(ag + 4, w * f2.x, w * f2.y, w * f3.x, w * f3.y);
    } else {
        uint2 h4 = __ldg(reinterpret_cast<const uint2*>(row + 16));
        float2 f4 = __half22float2(u32_as_h2(h4.x));
        float2 f5 = __half22float2(u32_as_h2(h4.y));
        red4(ag + 8, w * f4.x, w * f4.y, w * f5.x, w * f5.y);
    }
}

// ---- K4: pointwise GRU-collapse, 4 threads per node (8 channels each) ----
// a[t] = dinv*agg[t] + dinv^2*x[t];  (1-z) = 0.5*(1 - tanh(zarg/2)), 0.5 in probs.
// tanh pair (tz,th) evaluated in ONE MUFU op via tanh.approx.f16x2.
__global__ void k_final4(const float* __restrict__ x, float* __restrict__ out, int n) {
    int tid = blockIdx.x * blockDim.x + threadIdx.x;
    int node = tid >> 2;
    int q = tid & 3;                   // channel-quarter 0..3
    if (node >= n) return;
    float di = g_dinv[node];
    float di2 = di * di;
    float4* ap = reinterpret_cast<float4*>(g_agg + (size_t)node * TT);
    const float4* xp = reinterpret_cast<const float4*>(x + (size_t)node * TT);
    float4 a0 = ap[0], a1 = ap[1], a2 = ap[2];
    float4 x0 = __ldg(xp + 0), x1 = __ldg(xp + 1), x2 = __ldg(xp + 2);
    // distributed re-zero of scratch for next graph replay
    if (q < 3) ap[q] = make_float4(0.f, 0.f, 0.f, 0.f);
    else g_deg[node] = 0.0f;
    float a[TT] = {
        fmaf(di, a0.x, di2 * x0.x), fmaf(di, a0.y, di2 * x0.y),
        fmaf(di, a0.z, di2 * x0.z), fmaf(di, a0.w, di2 * x0.w),
        fmaf(di, a1.x, di2 * x1.x), fmaf(di, a1.y, di2 * x1.y),
        fmaf(di, a1.z, di2 * x1.z), fmaf(di, a1.w, di2 * x1.w),
        fmaf(di, a2.x, di2 * x2.x), fmaf(di, a2.y, di2 * x2.y),
        fmaf(di, a2.z, di2 * x2.z), fmaf(di, a2.w, di2 * x2.w)};
    float p[TT];
    #pragma unroll
    for (int t = 0; t < TT; t++) p[t] = g_probs[t];
    float acc = 0.f;
    int c0 = q * (CC / 4);
    #pragma unroll
    for (int cc = 0; cc < CC / 4; cc++) {
        int c = c0 + cc;
        float az = 0.5f * g_az[c], bz = 0.5f * g_bz[c];
        float ah = g_ah[c], bh = g_bh[c];
        float hw = g_hw[c];
        float hc = 0.f;
        #pragma unroll
        for (int t = 0; t < TT; t++) {
            float zarg = fmaf(a[t], az, bz);               // zarg/2 (halved coefs)
            float harg = fmaf(a[t], ah, bh);
            unsigned pk = h2_as_u32(__floats2half2_rn(zarg, harg));
            __half2 th2 = u32_as_h2(tanh2_fast(pk));       // {tanh(zarg/2), tanh(harg)}
            float tz = __low2float(th2);
            float th = __high2float(th2);
            hc = fmaf(p[t], fmaf(-tz, th, th), hc);        // p*(1-tz)*th
        }
        acc = fmaf(fmaxf(hc, 0.f), hw, acc);
    }
    // reduce the 4 channel-quarters (lanes q=0..3 of the same node share a warp)
    acc += __shfl_xor_sync(0xFFFFFFFFu, acc, 1);
    acc += __shfl_xor_sync(0xFFFFFFFFu, acc, 2);
    if (q == 0) out[node] = acc + g_hb;
}

extern "C" void kernel_launch(void* const* d_in, const int* in_sizes, int n_in,
                              void* d_out, int out_size) {
    const float* x      = (const float*)d_in[0];
    const int*   ei     = (const int*)  d_in[1];
    const float* ew     = (const float*)d_in[2];
    const float* w_z    = (const float*)d_in[3];
    const float* b_z    = (const float*)d_in[4];
    // d_in[5], d_in[6]: w_r, b_r — reset gate multiplies H=0, unused
    const float* w_h    = (const float*)d_in[7];
    const float* b_h    = (const float*)d_in[8];
    const float* lw_z   = (const float*)d_in[9];
    const float* lb_z   = (const float*)d_in[10];
    // d_in[11], d_in[12]: lw_r, lb_r — unused
    const float* lw_h   = (const float*)d_in[13];
    const float* lb_h   = (const float*)d_in[14];
    const float* att    = (const float*)d_in[15];
    const float* head_w = (const float*)d_in[16];
    const float* head_b = (const float*)d_in[17];
    float* out = (float*)d_out;

    int n = in_sizes[0] / TT;       // x is [N, T]
    int e = in_sizes[2];            // edge_weight is [E]
    if (n > MAXN) n = MAXN;

    const int B = 256;
    int gn  = (n + B - 1) / B;
    int gn4 = (n * 4 + B - 1) / B;
    int degBlocks = ((e + 3) / 4 + B - 1) / B;
    int gsc = (e * 2 + B - 1) / B;   // 2 lanes per edge

    k_deg_consts<<<degBlocks + 1, B>>>(ei, ew, e, degBlocks,
                                       w_z, b_z, w_h, b_h, lw_z, lb_z, lw_h, lb_h,
                                       att, head_w, head_b);
    k_dinv_y<<<gn, B>>>(x, n);
    k_scatter2h<<<gsc, B>>>(ei, ew, e);
    k_final4<<<gn4, B>>>(x, out, n);
}

// round 10
// speedup vs baseline: 1.1060x; 1.1060x over previous
#include <cuda_runtime.h>
#include <cuda_fp16.h>
#include <cuda_bf16.h>

#define TT 12
#define CC 32
#define MAXN 131072

// ---- bit-cast helpers (nvcc lacks __half2_as_uint / __uint_as_half2) ----
__device__ __forceinline__ unsigned h2_as_u32(__half2 h) {
    union { __half2 h; unsigned u; } cvt; cvt.h = h; return cvt.u;
}
__device__ __forceinline__ __half2 u32_as_h2(unsigned u) {
    union { unsigned u; __half2 h; } cvt; cvt.u = u; return cvt.h;
}

// ---- scratch (static device globals; zero-initialized at load; kept zeroed by k_final) ----
__device__ float g_deg[MAXN];          // Σ incoming w; self-loop +1 folded into rsqrt; re-zeroed by k_final
__device__ float g_dinv[MAXN];
__device__ float g_y[MAXN * TT];       // y[s,t] = dinv[s] * x[s,t]
__device__ float g_agg[MAXN * TT];     // scattered Σ w*y[s]; re-zeroed by k_final
__device__ __half2 g_hz_a[CC], g_hz_b[CC];   // broadcast half2: az/2, bz/2
__device__ __half2 g_hh_a[CC], g_hh_b[CC];   // broadcast half2: ah, bh
__device__ __half2 g_p2[TT / 2];             // probs (0.5*softmax) as t-pairs
__device__ float g_hw[CC];
__device__ float g_hb;

__device__ __forceinline__ unsigned tanh2_fast(unsigned x) {  // tanh.approx on a half2 pair
    unsigned y;
    asm("tanh.approx.f16x2 %0, %1;" : "=r"(y) : "r"(x));
    return y;
}

// vectorized global reduction: 4 floats per op
__device__ __forceinline__ void red4(float* p, float a, float b, float c, float d) {
    asm volatile("red.global.add.v4.f32 [%0], {%1, %2, %3, %4};"
                 :: "l"(p), "f"(a), "f"(b), "f"(c), "f"(d) : "memory");
}

// ---- K1: deg accumulation (blocks [0, degBlocks)) + consts fold (block degBlocks) ----
__global__ void k_deg_consts(const int* __restrict__ ei, const float* __restrict__ ew, int e,
                             int degBlocks,
                             const float* __restrict__ w_z, const float* __restrict__ b_z,
                             const float* __restrict__ w_h, const float* __restrict__ b_h,
                             const float* __restrict__ lw_z, const float* __restrict__ lb_z,
                             const float* __restrict__ lw_h, const float* __restrict__ lb_h,
                             const float* __restrict__ att,
                             const float* __restrict__ head_w, const float* __restrict__ head_b) {
    if (blockIdx.x < (unsigned)degBlocks) {
        int base = (blockIdx.x * blockDim.x + threadIdx.x) * 4;
        if (base + 3 < e) {
            int4   d = *reinterpret_cast<const int4*>(ei + e + base);
            float4 w = *reinterpret_cast<const float4*>(ew + base);
            atomicAdd(&g_deg[d.x], w.x);
            atomicAdd(&g_deg[d.y], w.y);
            atomicAdd(&g_deg[d.z], w.z);
            atomicAdd(&g_deg[d.w], w.w);
        } else {
            for (int i = base; i < e; i++) atomicAdd(&g_deg[ei[e + i]], ew[i]);
        }
        return;
    }
    // ---- consts block ----
    int o = threadIdx.x;
    if (o < CC) {
        float az = 0.f, bz = 0.f, ah = 0.f, bh = 0.f;
        const float* rz = lw_z + o * 2 * CC;   // torch layout [C, 2C]; first C cols used
        const float* rh = lw_h + o * 2 * CC;
        #pragma unroll
        for (int c = 0; c < CC; c++) {
            az += w_z[c] * rz[c];
            bz += b_z[c] * rz[c];
            ah += w_h[c] * rh[c];
            bh += b_h[c] * rh[c];
        }
        g_hz_a[o] = __float2half2_rn(0.5f * az);
        g_hz_b[o] = __float2half2_rn(0.5f * (bz + lb_z[o]));
        g_hh_a[o] = __float2half2_rn(ah);
        g_hh_b[o] = __float2half2_rn(bh + lb_h[o]);
        g_hw[o] = head_w[o];
    }
    if (o == 0) {
        float m = -1e30f;
        for (int t = 0; t < TT; t++) m = fmaxf(m, att[t]);
        float ex[TT]; float sum = 0.f;
        for (int t = 0; t < TT; t++) { ex[t] = expf(att[t] - m); sum += ex[t]; }
        float inv = 0.5f / sum;                 // fold the 0.5 of (1-z)
        for (int t = 0; t < TT / 2; t++)
            g_p2[t] = __floats2half2_rn(ex[2 * t] * inv, ex[2 * t + 1] * inv);
        g_hb = head_b[0];
    }
}

// ---- K2: dinv + y = dinv*x ; one thread per float4 chunk (3 per node) ----
__global__ void k_dinv_y(const float* __restrict__ x, int n3) {
    int j = blockIdx.x * blockDim.x + threadIdx.x;
    if (j >= n3) return;
    int node = j / 3;
    int part = j - node * 3;
    float di = rsqrtf(1.0f + g_deg[node]);   // +1 = self-loop weight; always > 0
    if (part == 0) g_dinv[node] = di;
    float4 v = __ldg(reinterpret_cast<const float4*>(x) + j);
    reinterpret_cast<float4*>(g_y)[j] = make_float4(di * v.x, di * v.y, di * v.z, di * v.w);
}

// ---- K3: cooperative 3-lane edge scatter  agg[d,:] += w * y[s,:] ----
// 3 lanes handle one edge (lane part p = float4 chunk p of the 48B row) so the
// gather and the RED for one row coalesce into single L1tex line-wavefronts.
__global__ void k_scatter3(const int* __restrict__ ei, const float* __restrict__ ew, int e) {
    int lane = threadIdx.x & 31;
    if (lane >= 30) return;
    int warp = (blockIdx.x * blockDim.x + threadIdx.x) >> 5;
    int grp  = lane / 3;               // 0..9
    int part = lane - grp * 3;         // 0..2
    int i = warp * 10 + grp;           // edge id
    if (i >= e) return;
    int s = __ldg(ei + i);
    int d = __ldg(ei + e + i);
    float w = __ldg(ew + i);
    float4 v = __ldg(reinterpret_cast<const float4*>(g_y + (size_t)s * TT) + part);
    red4(g_agg + (size_t)d * TT + part * 4, w * v.x, w * v.y, w * v.z, w * v.w);
}

// ---- K4: pointwise GRU-collapse, 4 threads/node, fully packed half2 inner loop ----
// a[t] = dinv*(agg[t]+y[t]);  (1-z) = 0.5*(1 - tanh(zarg/2)); 0.5 folded into probs.
// Per (c, t-pair): 2 HFMA2 args, 2 tanh.f16x2, HMUL2+HSUB2, HFMA2 accumulate.
__global__ void k_final4(float* __restrict__ out, int n) {
    int tid = blockIdx.x * blockDim.x + threadIdx.x;
    int node = tid >> 2;
    int q = tid & 3;                   // channel-quarter 0..3
    if (node >= n) return;
    float di = g_dinv[node];
    float4* ap = reinterpret_cast<float4*>(g_agg + (size_t)node * TT);
    const float4* yp = reinterpret_cast<const float4*>(g_y + (size_t)node * TT);
    float4 a0 = ap[0], a1 = ap[1], a2 = ap[2];
    float4 y0 = yp[0], y1 = yp[1], y2 = yp[2];
    // distributed re-zero of scratch for next graph replay
    if (q < 3) ap[q] = make_float4(0.f, 0.f, 0.f, 0.f);
    else g_deg[node] = 0.0f;
    // convert node state to half2 t-pairs ONCE
    __half2 a2h[TT / 2];
    a2h[0] = __floats2half2_rn(di * (a0.x + y0.x), di * (a0.y + y0.y));
    a2h[1] = __floats2half2_rn(di * (a0.z + y0.z), di * (a0.w + y0.w));
    a2h[2] = __floats2half2_rn(di * (a1.x + y1.x), di * (a1.y + y1.y));
    a2h[3] = __floats2half2_rn(di * (a1.z + y1.z), di * (a1.w + y1.w));
    a2h[4] = __floats2half2_rn(di * (a2.x + y2.x), di * (a2.y + y2.y));
    a2h[5] = __floats2half2_rn(di * (a2.z + y2.z), di * (a2.w + y2.w));
    __half2 p2[TT / 2];
    #pragma unroll
    for (int t = 0; t < TT / 2; t++) p2[t] = g_p2[t];
    float acc = 0.f;
    int c0 = q * (CC / 4);
    #pragma unroll
    for (int cc = 0; cc < CC / 4; cc++) {
        int c = c0 + cc;
        __half2 za = g_hz_a[c], zb = g_hz_b[c];
        __half2 ha = g_hh_a[c], hb = g_hh_b[c];
        float hw = g_hw[c];
        __half2 hc2 = __float2half2_rn(0.f);
        #pragma unroll
        for (int t = 0; t < TT / 2; t++) {
            __half2 zarg = __hfma2(a2h[t], za, zb);
            __half2 harg = __hfma2(a2h[t], ha, hb);
            __half2 tz2 = u32_as_h2(tanh2_fast(h2_as_u32(zarg)));   // tanh(zarg/2)
            __half2 th2 = u32_as_h2(tanh2_fast(h2_as_u32(harg)));   // tanh(harg)
            __half2 term = __hsub2(th2, __hmul2(tz2, th2));          // (1-tz)*th
            hc2 = __hfma2(p2[t], term, hc2);
        }
        float hc = __low2float(hc2) + __high2float(hc2);
        acc = fmaf(fmaxf(hc, 0.f), hw, acc);
    }
    // reduce the 4 channel-quarters (lanes q=0..3 of the same node share a warp)
    acc += __shfl_xor_sync(0xFFFFFFFFu, acc, 1);
    acc += __shfl_xor_sync(0xFFFFFFFFu, acc, 2);
    if (q == 0) out[node] = acc + g_hb;
}

extern "C" void kernel_launch(void* const* d_in, const int* in_sizes, int n_in,
                              void* d_out, int out_size) {
    const float* x      = (const float*)d_in[0];
    const int*   ei     = (const int*)  d_in[1];
    const float* ew     = (const float*)d_in[2];
    const float* w_z    = (const float*)d_in[3];
    const float* b_z    = (const float*)d_in[4];
    // d_in[5], d_in[6]: w_r, b_r — reset gate multiplies H=0, unused
    const float* w_h    = (const float*)d_in[7];
    const float* b_h    = (const float*)d_in[8];
    const float* lw_z   = (const float*)d_in[9];
    const float* lb_z   = (const float*)d_in[10];
    // d_in[11], d_in[12]: lw_r, lb_r — unused
    const float* lw_h   = (const float*)d_in[13];
    const float* lb_h   = (const float*)d_in[14];
    const float* att    = (const float*)d_in[15];
    const float* head_w = (const float*)d_in[16];
    const float* head_b = (const float*)d_in[17];
    float* out = (float*)d_out;

    int n = in_sizes[0] / TT;       // x is [N, T]
    int e = in_sizes[2];            // edge_weight is [E]
    if (n > MAXN) n = MAXN;

    const int B = 256;
    int n3  = n * 3;
    int gn3 = (n3 + B - 1) / B;
    int gn4 = (n * 4 + B - 1) / B;
    int degBlocks = ((e + 3) / 4 + B - 1) / B;
    int gsc = (e + 79) / 80;        // 10 edges per warp, 8 warps/block

    k_deg_consts<<<degBlocks + 1, B>>>(ei, ew, e, degBlocks,
                                       w_z, b_z, w_h, b_h, lw_z, lb_z, lw_h, lb_h,
                                       att, head_w, head_b);
    k_dinv_y<<<gn3, B>>>(x, n3);
    k_scatter3<<<gsc, B>>>(ei, ew, e);
    k_final4<<<gn4, B>>>(out, n);
}